// round 2
// baseline (speedup 1.0000x reference)
#include <cuda_runtime.h>
#include <cstdint>

#define H   2048
#define ISZ 4096
#define NE  8
#define T   2048

// ---------------- scratch (device globals: no allocations allowed) ----------
__device__ float g_act[4096UL * 4096UL];   // rows 0..2047 shared-expert act, 2048..4095 routed (compacted)
__device__ float g_scale[T];
__device__ float g_scale_perm[T];
__device__ int   g_eid[T];
__device__ int   g_perm[T];
__device__ int   g_off[NE + 1];

// ---------------- async-copy helpers ----------------------------------------
__device__ __forceinline__ void cp16(uint32_t s, const void* g) {
    asm volatile("cp.async.cg.shared.global [%0], [%1], 16;\n" :: "r"(s), "l"(g));
}
__device__ __forceinline__ void cp_commit() { asm volatile("cp.async.commit_group;\n"); }
__device__ __forceinline__ void cp_wait0()  { asm volatile("cp.async.wait_group 0;\n"); }

#define MMA_TF32(d, a, b)                                                      \
    asm volatile("mma.sync.aligned.m16n8k8.row.col.f32.tf32.tf32.f32 "         \
                 "{%0,%1,%2,%3},{%4,%5,%6,%7},{%8,%9},{%0,%1,%2,%3};"          \
                 : "+f"(d[0]), "+f"(d[1]), "+f"(d[2]), "+f"(d[3])              \
                 : "r"(a[0]), "r"(a[1]), "r"(a[2]), "r"(a[3]),                 \
                   "r"(b[0]), "r"(b[1]))

// 3xTF32 split: f = hi + lo (hi RNA-rounded tf32, lo the residual as tf32)
__device__ __forceinline__ uint32_t f2tf(float f) {
    uint32_t r;
    asm("cvt.rna.tf32.f32 %0, %1;" : "=r"(r) : "f"(f));
    return r;
}
__device__ __forceinline__ void tfsplit(float f, uint32_t& hi, uint32_t& lo) {
    hi = f2tf(f);
    lo = f2tf(f - __uint_as_float(hi));
}

// ---------------- router: top-1 argmax + sigmoid scale -----------------------
__global__ void router_kernel(const float* __restrict__ x, const float* __restrict__ rw) {
    const int t = blockIdx.x;
    const int tid = threadIdx.x;
    float acc[NE];
#pragma unroll
    for (int e = 0; e < NE; e++) acc[e] = 0.f;
    const float* xr = x + (size_t)t * H;
    for (int h = tid; h < H; h += 256) {
        float xv = xr[h];
#pragma unroll
        for (int e = 0; e < NE; e++) acc[e] += xv * rw[e * H + h];
    }
#pragma unroll
    for (int e = 0; e < NE; e++)
#pragma unroll
        for (int o = 16; o > 0; o >>= 1) acc[e] += __shfl_xor_sync(0xffffffffu, acc[e], o);
    __shared__ float red[NE][8];
    if ((tid & 31) == 0) {
#pragma unroll
        for (int e = 0; e < NE; e++) red[e][tid >> 5] = acc[e];
    }
    __syncthreads();
    if (tid == 0) {
        float best = -1e30f; int be = 0;
#pragma unroll
        for (int e = 0; e < NE; e++) {
            float v = 0.f;
#pragma unroll
            for (int w = 0; w < 8; w++) v += red[e][w];
            if (v > best) { best = v; be = e; }   // first index wins ties (matches top_k)
        }
        g_scale[t] = 1.f / (1.f + expf(-best));
        g_eid[t] = be;
    }
}

// ---------------- bucket tokens by expert (single block) ---------------------
__global__ void bucket_kernel() {
    __shared__ int cnt[NE], cur[NE], soff[NE + 1];
    const int tid = threadIdx.x;
    if (tid < NE) cnt[tid] = 0;
    __syncthreads();
    for (int t = tid; t < T; t += 256) atomicAdd(&cnt[g_eid[t]], 1);
    __syncthreads();
    if (tid == 0) {
        int a = 0;
        for (int e = 0; e < NE; e++) { soff[e] = a; cur[e] = a; a += cnt[e]; }
        soff[NE] = a;
        for (int i = 0; i <= NE; i++) g_off[i] = soff[i];
    }
    __syncthreads();
    for (int t = tid; t < T; t += 256) {
        int e = g_eid[t];
        int p = atomicAdd(&cur[e], 1);
        g_perm[p] = t;
        g_scale_perm[p] = g_scale[t];
    }
}

// ---------------- GEMM1: [M,2048] x [2048, gate|up 64-col tiles] + SwiGLU ----
// blockIdx.z: 0..7 routed experts (compacted rows via g_perm), 8 = shared expert.
// Block tile: 128 rows x (64 gate + 64 up) cols, BK=16, 3xTF32 mma, 2-stage cp.async.
__global__ __launch_bounds__(256) void gemm1_kernel(
    const float* __restrict__ x, const float* __restrict__ gup,
    const float* __restrict__ sg, const float* __restrict__ su)
{
    __shared__ float As[2][128 * 20];       // padded stride 20 (16B-aligned rows)
    __shared__ float Bs[2][2][16 * 68];     // [stage][gate/up], stride 68
    const int e = blockIdx.z;
    const int nTile = blockIdx.x;
    int M, offE, actBase, ldb;
    const float *pg, *pu;
    if (e < NE) {
        offE = g_off[e]; M = g_off[e + 1] - offE;
        if ((int)(blockIdx.y * 128) >= M) return;
        pg = gup + (size_t)e * H * (2 * ISZ) + nTile * 64;
        pu = pg + ISZ;
        ldb = 2 * ISZ;
        actBase = T + offE;
    } else {
        offE = 0; M = T;
        pg = sg + nTile * 64; pu = su + nTile * 64; ldb = ISZ;
        actBase = 0;
    }
    const int tid = threadIdx.x;
    const int lane = tid & 31, warp = tid >> 5;
    const int wm = warp & 3, wn = warp >> 2;       // 4 M-warps x 2 N-warps

    // A loader: thread -> rows (tid>>2) and (tid>>2)+64, 16B chunk (tid&3)*4
    const int arow0 = tid >> 2;
    const int akc = (tid & 3) * 4;
    const int lr0 = blockIdx.y * 128 + arow0, lr1 = lr0 + 64;
    const float *aptr0, *aptr1;
    if (e < NE) {
        aptr0 = x + (size_t)g_perm[offE + min(lr0, M - 1)] * H + akc;
        aptr1 = x + (size_t)g_perm[offE + min(lr1, M - 1)] * H + akc;
    } else {
        aptr0 = x + (size_t)lr0 * H + akc;
        aptr1 = x + (size_t)lr1 * H + akc;
    }
    const uint32_t sa0 = (uint32_t)__cvta_generic_to_shared(&As[0][arow0 * 20 + akc]);
    const uint32_t sa1 = (uint32_t)__cvta_generic_to_shared(&As[0][(arow0 + 64) * 20 + akc]);

    // B loader: rows 0..15, 16 chunks/row per half. thread -> (gate, up) chunk pair.
    const int brow = tid >> 4;
    const int bnc = (tid & 15) * 4;
    const float* bg = pg + (size_t)brow * ldb + bnc;
    const float* bu = pu + (size_t)brow * ldb + bnc;
    const uint32_t sbg = (uint32_t)__cvta_generic_to_shared(&Bs[0][0][brow * 68 + bnc]);
    const uint32_t sbu = (uint32_t)__cvta_generic_to_shared(&Bs[0][1][brow * 68 + bnc]);

    float acc[2][2][4][4];
#pragma unroll
    for (int h = 0; h < 2; h++)
#pragma unroll
        for (int mi = 0; mi < 2; mi++)
#pragma unroll
            for (int ni = 0; ni < 4; ni++)
#pragma unroll
                for (int r = 0; r < 4; r++) acc[h][mi][ni][r] = 0.f;

    const int ASTG = 128 * 20 * 4;
    const int BSTG = 2 * 16 * 68 * 4;

    cp16(sa0, aptr0); cp16(sa1, aptr1);
    cp16(sbg, bg);    cp16(sbu, bu);
    cp_commit(); cp_wait0();
    __syncthreads();

    const int KT = H / 16;
    for (int kt = 0; kt < KT; ++kt) {
        const int s = kt & 1;
        if (kt + 1 < KT) {
            const int k0 = (kt + 1) * 16;
            const int s2 = s ^ 1;
            cp16(sa0 + s2 * ASTG, aptr0 + k0);
            cp16(sa1 + s2 * ASTG, aptr1 + k0);
            cp16(sbg + s2 * BSTG, bg + (size_t)k0 * ldb);
            cp16(sbu + s2 * BSTG, bu + (size_t)k0 * ldb);
            cp_commit();
        }
        const float* A_ = As[s];
#pragma unroll
        for (int ks = 0; ks < 2; ++ks) {
            const int k = ks * 8;
            uint32_t ah[2][4], al[2][4];
#pragma unroll
            for (int mi = 0; mi < 2; ++mi) {
                const int r = wm * 32 + mi * 16 + (lane >> 2);
                const int c = k + (lane & 3);
                tfsplit(A_[r * 20 + c],           ah[mi][0], al[mi][0]);
                tfsplit(A_[(r + 8) * 20 + c],     ah[mi][1], al[mi][1]);
                tfsplit(A_[r * 20 + c + 4],       ah[mi][2], al[mi][2]);
                tfsplit(A_[(r + 8) * 20 + c + 4], ah[mi][3], al[mi][3]);
            }
            uint32_t bh[2][4][2], bl[2][4][2];
#pragma unroll
            for (int hh = 0; hh < 2; ++hh) {
                const float* B_ = Bs[s][hh];
#pragma unroll
                for (int ni = 0; ni < 4; ++ni) {
                    const int cidx = wn * 32 + ni * 8 + (lane >> 2);
                    const int rk = k + (lane & 3);
                    tfsplit(B_[rk * 68 + cidx],       bh[hh][ni][0], bl[hh][ni][0]);
                    tfsplit(B_[(rk + 4) * 68 + cidx], bh[hh][ni][1], bl[hh][ni][1]);
                }
            }
#pragma unroll
            for (int hh = 0; hh < 2; ++hh)
#pragma unroll
                for (int mi = 0; mi < 2; ++mi)
#pragma unroll
                    for (int ni = 0; ni < 4; ++ni) {
                        MMA_TF32(acc[hh][mi][ni], al[mi], bh[hh][ni]);
                        MMA_TF32(acc[hh][mi][ni], ah[mi], bl[hh][ni]);
                        MMA_TF32(acc[hh][mi][ni], ah[mi], bh[hh][ni]);
                    }
        }
        if (kt + 1 < KT) cp_wait0();
        __syncthreads();
    }

    // epilogue: act = (s*up) * silu(s*gate)  [scale is a row scale, applied post-GEMM]
#pragma unroll
    for (int mi = 0; mi < 2; ++mi) {
        const int r0 = blockIdx.y * 128 + wm * 32 + mi * 16 + (lane >> 2);
        const int r1 = r0 + 8;
        const bool v0 = r0 < M, v1 = r1 < M;
        float s0 = 1.f, s1 = 1.f;
        if (e < NE) {
            s0 = v0 ? g_scale_perm[offE + r0] : 0.f;
            s1 = v1 ? g_scale_perm[offE + r1] : 0.f;
        }
#pragma unroll
        for (int ni = 0; ni < 4; ++ni) {
            const int col = nTile * 64 + wn * 32 + ni * 8 + (lane & 3) * 2;
            if (v0) {
                float gA = s0 * acc[0][mi][ni][0], gB = s0 * acc[0][mi][ni][1];
                float uA = s0 * acc[1][mi][ni][0], uB = s0 * acc[1][mi][ni][1];
                float a0 = uA * (gA / (1.f + expf(-gA)));
                float a1 = uB * (gB / (1.f + expf(-gB)));
                *(float2*)&g_act[(size_t)(actBase + r0) * ISZ + col] = make_float2(a0, a1);
            }
            if (v1) {
                float gA = s1 * acc[0][mi][ni][2], gB = s1 * acc[0][mi][ni][3];
                float uA = s1 * acc[1][mi][ni][2], uB = s1 * acc[1][mi][ni][3];
                float a0 = uA * (gA / (1.f + expf(-gA)));
                float a1 = uB * (gB / (1.f + expf(-gB)));
                *(float2*)&g_act[(size_t)(actBase + r1) * ISZ + col] = make_float2(a0, a1);
            }
        }
    }
}

// ---------------- GEMM2: act [M,4096] x down [4096,2048] ---------------------
// routed=0: shared expert, plain store (runs first, initializes out).
// routed=1: grouped per expert, scatter-add via g_perm (runs second).
__global__ __launch_bounds__(256) void gemm2_kernel(
    const float* __restrict__ dwn, const float* __restrict__ sdwn,
    float* __restrict__ out, int routed)
{
    __shared__ float As[2][128 * 20];
    __shared__ float Bs[2][16 * 132];
    int M, offE, actBase;
    const float* Bd;
    const int nTile = blockIdx.x;
    if (routed) {
        const int e = blockIdx.z;
        offE = g_off[e]; M = g_off[e + 1] - offE;
        if ((int)(blockIdx.y * 128) >= M) return;
        actBase = T + offE;
        Bd = dwn + (size_t)e * ISZ * H + nTile * 128;
    } else {
        offE = 0; M = T; actBase = 0;
        Bd = sdwn + nTile * 128;
    }
    const int tid = threadIdx.x;
    const int lane = tid & 31, warp = tid >> 5;
    const int wm = warp & 3, wn = warp >> 2;

    const int arow0 = tid >> 2;
    const int akc = (tid & 3) * 4;
    const int lr0 = blockIdx.y * 128 + arow0, lr1 = lr0 + 64;
    const float* aptr0 = g_act + (size_t)(actBase + min(lr0, M - 1)) * ISZ + akc;
    const float* aptr1 = g_act + (size_t)(actBase + min(lr1, M - 1)) * ISZ + akc;
    const uint32_t sa0 = (uint32_t)__cvta_generic_to_shared(&As[0][arow0 * 20 + akc]);
    const uint32_t sa1 = (uint32_t)__cvta_generic_to_shared(&As[0][(arow0 + 64) * 20 + akc]);

    const int brow = tid >> 5;            // 0..7
    const int bnc = (tid & 31) * 4;       // 32 chunks per 128-float row
    const float* bptr0 = Bd + (size_t)brow * H + bnc;
    const float* bptr1 = Bd + (size_t)(brow + 8) * H + bnc;
    const uint32_t sb0 = (uint32_t)__cvta_generic_to_shared(&Bs[0][brow * 132 + bnc]);
    const uint32_t sb1 = (uint32_t)__cvta_generic_to_shared(&Bs[0][(brow + 8) * 132 + bnc]);

    float acc[2][8][4];
#pragma unroll
    for (int mi = 0; mi < 2; mi++)
#pragma unroll
        for (int ni = 0; ni < 8; ni++)
#pragma unroll
            for (int r = 0; r < 4; r++) acc[mi][ni][r] = 0.f;

    const int ASTG = 128 * 20 * 4;
    const int BSTG = 16 * 132 * 4;

    cp16(sa0, aptr0); cp16(sa1, aptr1);
    cp16(sb0, bptr0); cp16(sb1, bptr1);
    cp_commit(); cp_wait0();
    __syncthreads();

    const int KT = ISZ / 16;
    for (int kt = 0; kt < KT; ++kt) {
        const int s = kt & 1;
        if (kt + 1 < KT) {
            const int k0 = (kt + 1) * 16;
            const int s2 = s ^ 1;
            cp16(sa0 + s2 * ASTG, aptr0 + k0);
            cp16(sa1 + s2 * ASTG, aptr1 + k0);
            cp16(sb0 + s2 * BSTG, bptr0 + (size_t)k0 * H);
            cp16(sb1 + s2 * BSTG, bptr1 + (size_t)k0 * H);
            cp_commit();
        }
        const float* A_ = As[s];
        const float* B_ = Bs[s];
#pragma unroll
        for (int ks = 0; ks < 2; ++ks) {
            const int k = ks * 8;
            uint32_t ah[2][4], al[2][4];
#pragma unroll
            for (int mi = 0; mi < 2; ++mi) {
                const int r = wm * 32 + mi * 16 + (lane >> 2);
                const int c = k + (lane & 3);
                tfsplit(A_[r * 20 + c],           ah[mi][0], al[mi][0]);
                tfsplit(A_[(r + 8) * 20 + c],     ah[mi][1], al[mi][1]);
                tfsplit(A_[r * 20 + c + 4],       ah[mi][2], al[mi][2]);
                tfsplit(A_[(r + 8) * 20 + c + 4], ah[mi][3], al[mi][3]);
            }
            uint32_t bh[8][2], bl[8][2];
#pragma unroll
            for (int ni = 0; ni < 8; ++ni) {
                const int cidx = wn * 64 + ni * 8 + (lane >> 2);
                const int rk = k + (lane & 3);
                tfsplit(B_[rk * 132 + cidx],       bh[ni][0], bl[ni][0]);
                tfsplit(B_[(rk + 4) * 132 + cidx], bh[ni][1], bl[ni][1]);
            }
#pragma unroll
            for (int mi = 0; mi < 2; ++mi)
#pragma unroll
                for (int ni = 0; ni < 8; ++ni) {
                    MMA_TF32(acc[mi][ni], al[mi], bh[ni]);
                    MMA_TF32(acc[mi][ni], ah[mi], bl[ni]);
                    MMA_TF32(acc[mi][ni], ah[mi], bh[ni]);
                }
        }
        if (kt + 1 < KT) cp_wait0();
        __syncthreads();
    }

#pragma unroll
    for (int mi = 0; mi < 2; ++mi) {
        const int r0 = blockIdx.y * 128 + wm * 32 + mi * 16 + (lane >> 2);
        const int r1 = r0 + 8;
        const bool v0 = r0 < M, v1 = r1 < M;
        int t0 = 0, t1 = 0;
        if (routed) {
            if (v0) t0 = g_perm[offE + r0];
            if (v1) t1 = g_perm[offE + r1];
        } else { t0 = r0; t1 = r1; }
#pragma unroll
        for (int ni = 0; ni < 8; ++ni) {
            const int col = nTile * 128 + wn * 64 + ni * 8 + (lane & 3) * 2;
            if (v0) {
                float2* p = (float2*)&out[(size_t)t0 * H + col];
                if (routed) {
                    float2 v = *p;
                    v.x += acc[mi][ni][0]; v.y += acc[mi][ni][1];
                    *p = v;
                } else {
                    *p = make_float2(acc[mi][ni][0], acc[mi][ni][1]);
                }
            }
            if (v1) {
                float2* p = (float2*)&out[(size_t)t1 * H + col];
                if (routed) {
                    float2 v = *p;
                    v.x += acc[mi][ni][2]; v.y += acc[mi][ni][3];
                    *p = v;
                } else {
                    *p = make_float2(acc[mi][ni][2], acc[mi][ni][3]);
                }
            }
        }
    }
}

// ---------------- launch -----------------------------------------------------
extern "C" void kernel_launch(void* const* d_in, const int* in_sizes, int n_in,
                              void* d_out, int out_size) {
    const float* x   = (const float*)d_in[0];
    const float* rw  = (const float*)d_in[1];
    const float* gup = (const float*)d_in[2];
    const float* dwn = (const float*)d_in[3];
    const float* sg  = (const float*)d_in[4];
    const float* su  = (const float*)d_in[5];
    const float* sd  = (const float*)d_in[6];
    float* out = (float*)d_out;

    router_kernel<<<T, 256>>>(x, rw);
    bucket_kernel<<<1, 256>>>();
    gemm1_kernel<<<dim3(ISZ / 64, T / 128, NE + 1), 256>>>(x, gup, sg, su);
    gemm2_kernel<<<dim3(H / 128, T / 128, 1), 256>>>(dwn, sd, out, 0);   // shared: writes out
    gemm2_kernel<<<dim3(H / 128, T / 128, NE), 256>>>(dwn, sd, out, 1);  // routed: adds
}

// round 3
// speedup vs baseline: 1.3384x; 1.3384x over previous
#include <cuda_runtime.h>
#include <cuda_bf16.h>
#include <cstdint>

#define H   2048
#define ISZ 4096
#define NE  8
#define T   2048

// ---------------- scratch -----------------------------------------------------
__device__ float g_act[4096UL * 4096UL];   // rows 0..2047 shared act, 2048..4095 routed (compacted)
__device__ float g_scale[T];
__device__ float g_scale_perm[T];
__device__ int   g_eid[T];
__device__ int   g_perm[T];
__device__ int   g_off[NE + 1];

#define MMA_BF16(d, a, b)                                                      \
    asm volatile("mma.sync.aligned.m16n8k16.row.col.f32.bf16.bf16.f32 "        \
                 "{%0,%1,%2,%3},{%4,%5,%6,%7},{%8,%9},{%0,%1,%2,%3};"          \
                 : "+f"(d[0]), "+f"(d[1]), "+f"(d[2]), "+f"(d[3])              \
                 : "r"(a[0]), "r"(a[1]), "r"(a[2]), "r"(a[3]),                 \
                   "r"(b[0]), "r"(b[1]))

// split pair (f0,f1) -> packed bf16x2 hi word + bf16x2 lo (residual) word.
// word low half = f0 (even k), high half = f1 (odd k): HMMA operand order.
__device__ __forceinline__ void bpair(float f0, float f1, uint32_t& hw, uint32_t& lw) {
    __nv_bfloat162 h = __floats2bfloat162_rn(f0, f1);
    uint32_t hu = *reinterpret_cast<uint32_t*>(&h);
    float r0 = f0 - __uint_as_float(hu << 16);
    float r1 = f1 - __uint_as_float(hu & 0xffff0000u);
    __nv_bfloat162 l = __floats2bfloat162_rn(r0, r1);
    hw = hu;
    lw = *reinterpret_cast<uint32_t*>(&l);
}
__device__ __forceinline__ void bsplit4(float4 v, uint32_t& h0, uint32_t& h1,
                                        uint32_t& l0, uint32_t& l1) {
    bpair(v.x, v.y, h0, l0);
    bpair(v.z, v.w, h1, l1);
}

// ---------------- router ------------------------------------------------------
__global__ void router_kernel(const float* __restrict__ x, const float* __restrict__ rw) {
    const int t = blockIdx.x;
    const int tid = threadIdx.x;
    float acc[NE];
#pragma unroll
    for (int e = 0; e < NE; e++) acc[e] = 0.f;
    const float* xr = x + (size_t)t * H;
    for (int h = tid; h < H; h += 256) {
        float xv = xr[h];
#pragma unroll
        for (int e = 0; e < NE; e++) acc[e] += xv * rw[e * H + h];
    }
#pragma unroll
    for (int e = 0; e < NE; e++)
#pragma unroll
        for (int o = 16; o > 0; o >>= 1) acc[e] += __shfl_xor_sync(0xffffffffu, acc[e], o);
    __shared__ float red[NE][8];
    if ((tid & 31) == 0) {
#pragma unroll
        for (int e = 0; e < NE; e++) red[e][tid >> 5] = acc[e];
    }
    __syncthreads();
    if (tid == 0) {
        float best = -1e30f; int be = 0;
#pragma unroll
        for (int e = 0; e < NE; e++) {
            float v = 0.f;
#pragma unroll
            for (int w = 0; w < 8; w++) v += red[e][w];
            if (v > best) { best = v; be = e; }
        }
        g_scale[t] = 1.f / (1.f + expf(-best));
        g_eid[t] = be;
    }
}

// ---------------- bucket ------------------------------------------------------
__global__ void bucket_kernel() {
    __shared__ int cnt[NE], cur[NE];
    const int tid = threadIdx.x;
    if (tid < NE) cnt[tid] = 0;
    __syncthreads();
    for (int t = tid; t < T; t += 256) atomicAdd(&cnt[g_eid[t]], 1);
    __syncthreads();
    if (tid == 0) {
        int a = 0;
        for (int e = 0; e < NE; e++) { g_off[e] = a; cur[e] = a; a += cnt[e]; }
        g_off[NE] = a;
    }
    __syncthreads();
    for (int t = tid; t < T; t += 256) {
        int e = g_eid[t];
        int p = atomicAdd(&cur[e], 1);
        g_perm[p] = t;
        g_scale_perm[p] = g_scale[t];
    }
}

// ---------------- GEMM1: x[M,2048] x (gate|up)[2048, 64+64 cols] + SwiGLU -----
// grid: (mTile<=16, nTile=64, expert 0..8). 3xBF16, pre-split SMEM, BK=16.
__global__ __launch_bounds__(256) void gemm1_kernel(
    const float* __restrict__ x, const float* __restrict__ gup,
    const float* __restrict__ sg, const float* __restrict__ su)
{
    __shared__ uint32_t As[2][2][128][12];      // [buf][h/l][row][kword]
    __shared__ uint32_t Bs[2][2][2][64][12];    // [buf][h/l][gate/up][n][kword]
    const int mTile = blockIdx.x, nTile = blockIdx.y, e = blockIdx.z;
    int M, offE, actBase, ldb;
    const float *pg, *pu;
    if (e < NE) {
        offE = g_off[e]; M = g_off[e + 1] - offE;
        if (mTile * 128 >= M) return;
        pg = gup + (size_t)e * H * (2 * ISZ) + nTile * 64;
        pu = pg + ISZ; ldb = 2 * ISZ; actBase = T + offE;
    } else {
        offE = 0; M = T;
        pg = sg + nTile * 64; pu = su + nTile * 64; ldb = ISZ; actBase = 0;
    }
    const int tid = threadIdx.x, lane = tid & 31, warp = tid >> 5;
    const int wm = warp & 3, wn = warp >> 2;

    // A loader: row = tid>>1, 8 floats at (tid&1)*8
    const int arow = tid >> 1;
    const int akc = (tid & 1) * 8;
    const int aw0 = (tid & 1) * 4;
    const int lr = mTile * 128 + arow;
    const float* aptr;
    if (e < NE) aptr = x + (size_t)g_perm[offE + min(lr, M - 1)] * H + akc;
    else        aptr = x + (size_t)lr * H + akc;

    // B loader: half = tid>>7, kp = tid&7, n0 = ((tid&127)>>3)*4
    const int bhalf = tid >> 7, bkp = tid & 7, bn0 = ((tid & 127) >> 3) * 4;
    const float* bbase = bhalf ? pu : pg;
    const float* bptr0 = bbase + (size_t)(2 * bkp) * ldb + bn0;
    const float* bptr1 = bbase + (size_t)(2 * bkp + 1) * ldb + bn0;

    float acc[2][2][4][4];
#pragma unroll
    for (int h = 0; h < 2; h++)
#pragma unroll
        for (int mi = 0; mi < 2; mi++)
#pragma unroll
            for (int ni = 0; ni < 4; ni++)
#pragma unroll
                for (int r = 0; r < 4; r++) acc[h][mi][ni][r] = 0.f;

    // prologue: fill buffer 0
    {
        float4 a0 = *(const float4*)aptr;
        float4 a1 = *(const float4*)(aptr + 4);
        float4 b0 = *(const float4*)bptr0;
        float4 b1 = *(const float4*)bptr1;
        uint32_t h0, h1, h2, h3, l0, l1, l2, l3;
        bsplit4(a0, h0, h1, l0, l1); bsplit4(a1, h2, h3, l2, l3);
        *(uint4*)&As[0][0][arow][aw0] = make_uint4(h0, h1, h2, h3);
        *(uint4*)&As[0][1][arow][aw0] = make_uint4(l0, l1, l2, l3);
        const float* pb0 = &b0.x; const float* pb1 = &b1.x;
#pragma unroll
        for (int j = 0; j < 4; j++) {
            uint32_t hw, lw;
            bpair(pb0[j], pb1[j], hw, lw);
            Bs[0][0][bhalf][bn0 + j][bkp] = hw;
            Bs[0][1][bhalf][bn0 + j][bkp] = lw;
        }
    }
    __syncthreads();

    const int KT = H / 16;
    for (int kt = 0; kt < KT; ++kt) {
        const int s = kt & 1;
        float4 a0, a1, b0, b1;
        if (kt + 1 < KT) {
            const float* ap = aptr + (kt + 1) * 16;
            a0 = *(const float4*)ap;
            a1 = *(const float4*)(ap + 4);
            const size_t koff = (size_t)(kt + 1) * 16 * ldb;
            b0 = *(const float4*)(bptr0 + koff);
            b1 = *(const float4*)(bptr1 + koff);
        }

        // compute from buffer s
        uint32_t ah[2][4], al[2][4];
        const int w = lane & 3;
#pragma unroll
        for (int mi = 0; mi < 2; ++mi) {
            const int r = wm * 32 + mi * 16 + (lane >> 2);
            ah[mi][0] = As[s][0][r][w];     ah[mi][1] = As[s][0][r + 8][w];
            ah[mi][2] = As[s][0][r][w + 4]; ah[mi][3] = As[s][0][r + 8][w + 4];
            al[mi][0] = As[s][1][r][w];     al[mi][1] = As[s][1][r + 8][w];
            al[mi][2] = As[s][1][r][w + 4]; al[mi][3] = As[s][1][r + 8][w + 4];
        }
#pragma unroll
        for (int hh = 0; hh < 2; ++hh) {
#pragma unroll
            for (int ni = 0; ni < 4; ++ni) {
                const int n = wn * 32 + ni * 8 + (lane >> 2);
                uint32_t bh[2] = { Bs[s][0][hh][n][w], Bs[s][0][hh][n][w + 4] };
                uint32_t bl[2] = { Bs[s][1][hh][n][w], Bs[s][1][hh][n][w + 4] };
#pragma unroll
                for (int mi = 0; mi < 2; ++mi) {
                    MMA_BF16(acc[hh][mi][ni], al[mi], bh);
                    MMA_BF16(acc[hh][mi][ni], ah[mi], bl);
                    MMA_BF16(acc[hh][mi][ni], ah[mi], bh);
                }
            }
        }

        if (kt + 1 < KT) {
            const int s2 = s ^ 1;
            uint32_t h0, h1, h2, h3, l0, l1, l2, l3;
            bsplit4(a0, h0, h1, l0, l1); bsplit4(a1, h2, h3, l2, l3);
            *(uint4*)&As[s2][0][arow][aw0] = make_uint4(h0, h1, h2, h3);
            *(uint4*)&As[s2][1][arow][aw0] = make_uint4(l0, l1, l2, l3);
            const float* pb0 = &b0.x; const float* pb1 = &b1.x;
#pragma unroll
            for (int j = 0; j < 4; j++) {
                uint32_t hw, lw;
                bpair(pb0[j], pb1[j], hw, lw);
                Bs[s2][0][bhalf][bn0 + j][bkp] = hw;
                Bs[s2][1][bhalf][bn0 + j][bkp] = lw;
            }
        }
        __syncthreads();
    }

    // epilogue: act = (s*up) * silu(s*gate)
#pragma unroll
    for (int mi = 0; mi < 2; ++mi) {
        const int r0 = mTile * 128 + wm * 32 + mi * 16 + (lane >> 2);
        const int r1 = r0 + 8;
        const bool v0 = r0 < M, v1 = r1 < M;
        float s0 = 1.f, s1 = 1.f;
        if (e < NE) {
            s0 = v0 ? g_scale_perm[offE + r0] : 0.f;
            s1 = v1 ? g_scale_perm[offE + r1] : 0.f;
        }
#pragma unroll
        for (int ni = 0; ni < 4; ++ni) {
            const int col = nTile * 64 + wn * 32 + ni * 8 + (lane & 3) * 2;
            if (v0) {
                float gA = s0 * acc[0][mi][ni][0], gB = s0 * acc[0][mi][ni][1];
                float uA = s0 * acc[1][mi][ni][0], uB = s0 * acc[1][mi][ni][1];
                float a0 = uA * (gA / (1.f + expf(-gA)));
                float a1 = uB * (gB / (1.f + expf(-gB)));
                *(float2*)&g_act[(size_t)(actBase + r0) * ISZ + col] = make_float2(a0, a1);
            }
            if (v1) {
                float gA = s1 * acc[0][mi][ni][2], gB = s1 * acc[0][mi][ni][3];
                float uA = s1 * acc[1][mi][ni][2], uB = s1 * acc[1][mi][ni][3];
                float a0 = uA * (gA / (1.f + expf(-gA)));
                float a1 = uB * (gB / (1.f + expf(-gB)));
                *(float2*)&g_act[(size_t)(actBase + r1) * ISZ + col] = make_float2(a0, a1);
            }
        }
    }
}

// ---------------- GEMM2: act[M,4096] x down[4096,2048] ------------------------
__global__ __launch_bounds__(256) void gemm2_kernel(
    const float* __restrict__ dwn, const float* __restrict__ sdwn,
    float* __restrict__ out, int routed)
{
    __shared__ uint32_t As[2][2][128][12];
    __shared__ uint32_t Bs[2][2][128][12];
    const int mTile = blockIdx.x, nTile = blockIdx.y;
    int M, offE, actBase;
    const float* Bd;
    if (routed) {
        const int e = blockIdx.z;
        offE = g_off[e]; M = g_off[e + 1] - offE;
        if (mTile * 128 >= M) return;
        actBase = T + offE;
        Bd = dwn + (size_t)e * ISZ * H + nTile * 128;
    } else {
        offE = 0; M = T; actBase = 0;
        Bd = sdwn + nTile * 128;
    }
    const int tid = threadIdx.x, lane = tid & 31, warp = tid >> 5;
    const int wm = warp & 3, wn = warp >> 2;

    const int arow = tid >> 1;
    const int akc = (tid & 1) * 8;
    const int aw0 = (tid & 1) * 4;
    const int lr = mTile * 128 + arow;
    const float* aptr = g_act + (size_t)(actBase + min(lr, M - 1)) * ISZ + akc;

    const int bkp = tid & 7, bn0 = (tid >> 3) * 4;   // n0: 0..124
    const float* bptr0 = Bd + (size_t)(2 * bkp) * H + bn0;
    const float* bptr1 = Bd + (size_t)(2 * bkp + 1) * H + bn0;

    float acc[2][8][4];
#pragma unroll
    for (int mi = 0; mi < 2; mi++)
#pragma unroll
        for (int ni = 0; ni < 8; ni++)
#pragma unroll
            for (int r = 0; r < 4; r++) acc[mi][ni][r] = 0.f;

    {
        float4 a0 = *(const float4*)aptr;
        float4 a1 = *(const float4*)(aptr + 4);
        float4 b0 = *(const float4*)bptr0;
        float4 b1 = *(const float4*)bptr1;
        uint32_t h0, h1, h2, h3, l0, l1, l2, l3;
        bsplit4(a0, h0, h1, l0, l1); bsplit4(a1, h2, h3, l2, l3);
        *(uint4*)&As[0][0][arow][aw0] = make_uint4(h0, h1, h2, h3);
        *(uint4*)&As[0][1][arow][aw0] = make_uint4(l0, l1, l2, l3);
        const float* pb0 = &b0.x; const float* pb1 = &b1.x;
#pragma unroll
        for (int j = 0; j < 4; j++) {
            uint32_t hw, lw;
            bpair(pb0[j], pb1[j], hw, lw);
            Bs[0][0][bn0 + j][bkp] = hw;
            Bs[0][1][bn0 + j][bkp] = lw;
        }
    }
    __syncthreads();

    const int KT = ISZ / 16;
    for (int kt = 0; kt < KT; ++kt) {
        const int s = kt & 1;
        float4 a0, a1, b0, b1;
        if (kt + 1 < KT) {
            const float* ap = aptr + (kt + 1) * 16;
            a0 = *(const float4*)ap;
            a1 = *(const float4*)(ap + 4);
            const size_t koff = (size_t)(kt + 1) * 16 * H;
            b0 = *(const float4*)(bptr0 + koff);
            b1 = *(const float4*)(bptr1 + koff);
        }

        uint32_t ah[2][4], al[2][4];
        const int w = lane & 3;
#pragma unroll
        for (int mi = 0; mi < 2; ++mi) {
            const int r = wm * 32 + mi * 16 + (lane >> 2);
            ah[mi][0] = As[s][0][r][w];     ah[mi][1] = As[s][0][r + 8][w];
            ah[mi][2] = As[s][0][r][w + 4]; ah[mi][3] = As[s][0][r + 8][w + 4];
            al[mi][0] = As[s][1][r][w];     al[mi][1] = As[s][1][r + 8][w];
            al[mi][2] = As[s][1][r][w + 4]; al[mi][3] = As[s][1][r + 8][w + 4];
        }
#pragma unroll
        for (int ni = 0; ni < 8; ++ni) {
            const int n = wn * 64 + ni * 8 + (lane >> 2);
            uint32_t bh[2] = { Bs[s][0][n][w], Bs[s][0][n][w + 4] };
            uint32_t bl[2] = { Bs[s][1][n][w], Bs[s][1][n][w + 4] };
#pragma unroll
            for (int mi = 0; mi < 2; ++mi) {
                MMA_BF16(acc[mi][ni], al[mi], bh);
                MMA_BF16(acc[mi][ni], ah[mi], bl);
                MMA_BF16(acc[mi][ni], ah[mi], bh);
            }
        }

        if (kt + 1 < KT) {
            const int s2 = s ^ 1;
            uint32_t h0, h1, h2, h3, l0, l1, l2, l3;
            bsplit4(a0, h0, h1, l0, l1); bsplit4(a1, h2, h3, l2, l3);
            *(uint4*)&As[s2][0][arow][aw0] = make_uint4(h0, h1, h2, h3);
            *(uint4*)&As[s2][1][arow][aw0] = make_uint4(l0, l1, l2, l3);
            const float* pb0 = &b0.x; const float* pb1 = &b1.x;
#pragma unroll
            for (int j = 0; j < 4; j++) {
                uint32_t hw, lw;
                bpair(pb0[j], pb1[j], hw, lw);
                Bs[s2][0][bn0 + j][bkp] = hw;
                Bs[s2][1][bn0 + j][bkp] = lw;
            }
        }
        __syncthreads();
    }

#pragma unroll
    for (int mi = 0; mi < 2; ++mi) {
        const int r0 = mTile * 128 + wm * 32 + mi * 16 + (lane >> 2);
        const int r1 = r0 + 8;
        const bool v0 = r0 < M, v1 = r1 < M;
        int t0 = 0, t1 = 0;
        if (routed) {
            if (v0) t0 = g_perm[offE + r0];
            if (v1) t1 = g_perm[offE + r1];
        } else { t0 = r0; t1 = r1; }
#pragma unroll
        for (int ni = 0; ni < 8; ++ni) {
            const int col = nTile * 128 + wn * 64 + ni * 8 + (lane & 3) * 2;
            if (v0) {
                float2* p = (float2*)&out[(size_t)t0 * H + col];
                if (routed) {
                    float2 v = *p;
                    v.x += acc[mi][ni][0]; v.y += acc[mi][ni][1];
                    *p = v;
                } else {
                    *p = make_float2(acc[mi][ni][0], acc[mi][ni][1]);
                }
            }
            if (v1) {
                float2* p = (float2*)&out[(size_t)t1 * H + col];
                if (routed) {
                    float2 v = *p;
                    v.x += acc[mi][ni][2]; v.y += acc[mi][ni][3];
                    *p = v;
                } else {
                    *p = make_float2(acc[mi][ni][2], acc[mi][ni][3]);
                }
            }
        }
    }
}

// ---------------- launch ------------------------------------------------------
extern "C" void kernel_launch(void* const* d_in, const int* in_sizes, int n_in,
                              void* d_out, int out_size) {
    const float* x   = (const float*)d_in[0];
    const float* rw  = (const float*)d_in[1];
    const float* gup = (const float*)d_in[2];
    const float* dwn = (const float*)d_in[3];
    const float* sg  = (const float*)d_in[4];
    const float* su  = (const float*)d_in[5];
    const float* sd  = (const float*)d_in[6];
    float* out = (float*)d_out;

    router_kernel<<<T, 256>>>(x, rw);
    bucket_kernel<<<1, 256>>>();
    gemm1_kernel<<<dim3(16, ISZ / 64, NE + 1), 256>>>(x, gup, sg, su);
    gemm2_kernel<<<dim3(16, H / 128, 1), 256>>>(dwn, sd, out, 0);   // shared: writes out
    gemm2_kernel<<<dim3(16, H / 128, NE), 256>>>(dwn, sd, out, 1);  // routed: adds
}

// round 4
// speedup vs baseline: 2.0252x; 1.5131x over previous
#include <cuda_runtime.h>
#include <cuda_bf16.h>
#include <cstdint>

#define H   2048
#define ISZ 4096
#define NE  8
#define T   2048

// ---------------- scratch -----------------------------------------------------
__device__ float g_act[4096UL * 4096UL];   // rows 0..2047 shared act, 2048..4095 routed (compacted)
__device__ float g_scale[T];
__device__ float g_scale_perm[T];
__device__ int   g_eid[T];
__device__ int   g_perm[T];
__device__ int   g_off[NE + 1];

#define MMA_BF16(d, a, b)                                                      \
    asm volatile("mma.sync.aligned.m16n8k16.row.col.f32.bf16.bf16.f32 "        \
                 "{%0,%1,%2,%3},{%4,%5,%6,%7},{%8,%9},{%0,%1,%2,%3};"          \
                 : "+f"(d[0]), "+f"(d[1]), "+f"(d[2]), "+f"(d[3])              \
                 : "r"(a[0]), "r"(a[1]), "r"(a[2]), "r"(a[3]),                 \
                   "r"(b[0]), "r"(b[1]))

__device__ __forceinline__ void ldsm_x4(uint32_t* r, uint32_t addr) {
    asm volatile("ldmatrix.sync.aligned.m8n8.x4.shared.b16 {%0,%1,%2,%3}, [%4];"
                 : "=r"(r[0]), "=r"(r[1]), "=r"(r[2]), "=r"(r[3]) : "r"(addr));
}
__device__ __forceinline__ void ldsm_x4t(uint32_t* r, uint32_t addr) {
    asm volatile("ldmatrix.sync.aligned.m8n8.x4.trans.shared.b16 {%0,%1,%2,%3}, [%4];"
                 : "=r"(r[0]), "=r"(r[1]), "=r"(r[2]), "=r"(r[3]) : "r"(addr));
}

// split pair (f0,f1) -> packed bf16x2 hi word + bf16x2 lo (residual) word.
__device__ __forceinline__ void bpair(float f0, float f1, uint32_t& hw, uint32_t& lw) {
    __nv_bfloat162 h = __floats2bfloat162_rn(f0, f1);
    uint32_t hu = *reinterpret_cast<uint32_t*>(&h);
    float r0 = f0 - __uint_as_float(hu << 16);
    float r1 = f1 - __uint_as_float(hu & 0xffff0000u);
    __nv_bfloat162 l = __floats2bfloat162_rn(r0, r1);
    hw = hu;
    lw = *reinterpret_cast<uint32_t*>(&l);
}
__device__ __forceinline__ void pack8(const float4& v0, const float4& v1, uint4& hi, uint4& lo) {
    uint32_t h0, h1, h2, h3, l0, l1, l2, l3;
    bpair(v0.x, v0.y, h0, l0); bpair(v0.z, v0.w, h1, l1);
    bpair(v1.x, v1.y, h2, l2); bpair(v1.z, v1.w, h3, l3);
    hi = make_uint4(h0, h1, h2, h3); lo = make_uint4(l0, l1, l2, l3);
}

// ---------------- router ------------------------------------------------------
__global__ void router_kernel(const float* __restrict__ x, const float* __restrict__ rw) {
    const int t = blockIdx.x;
    const int tid = threadIdx.x;
    float acc[NE];
#pragma unroll
    for (int e = 0; e < NE; e++) acc[e] = 0.f;
    const float* xr = x + (size_t)t * H;
    for (int h = tid; h < H; h += 256) {
        float xv = xr[h];
#pragma unroll
        for (int e = 0; e < NE; e++) acc[e] += xv * rw[e * H + h];
    }
#pragma unroll
    for (int e = 0; e < NE; e++)
#pragma unroll
        for (int o = 16; o > 0; o >>= 1) acc[e] += __shfl_xor_sync(0xffffffffu, acc[e], o);
    __shared__ float red[NE][8];
    if ((tid & 31) == 0) {
#pragma unroll
        for (int e = 0; e < NE; e++) red[e][tid >> 5] = acc[e];
    }
    __syncthreads();
    if (tid == 0) {
        float best = -1e30f; int be = 0;
#pragma unroll
        for (int e = 0; e < NE; e++) {
            float v = 0.f;
#pragma unroll
            for (int w = 0; w < 8; w++) v += red[e][w];
            if (v > best) { best = v; be = e; }
        }
        g_scale[t] = 1.f / (1.f + expf(-best));
        g_eid[t] = be;
    }
}

// ---------------- bucket ------------------------------------------------------
__global__ void bucket_kernel() {
    __shared__ int cnt[NE], cur[NE];
    const int tid = threadIdx.x;
    if (tid < NE) cnt[tid] = 0;
    __syncthreads();
    for (int t = tid; t < T; t += 256) atomicAdd(&cnt[g_eid[t]], 1);
    __syncthreads();
    if (tid == 0) {
        int a = 0;
        for (int e = 0; e < NE; e++) { g_off[e] = a; cur[e] = a; a += cnt[e]; }
        g_off[NE] = a;
    }
    __syncthreads();
    for (int t = tid; t < T; t += 256) {
        int e = g_eid[t];
        int p = atomicAdd(&cur[e], 1);
        g_perm[p] = t;
        g_scale_perm[p] = g_scale[t];
    }
}

// ---------------- GEMM1: x[M,2048] x (gate|up)[2048, 64+64] + SwiGLU ----------
__global__ __launch_bounds__(256) void gemm1_kernel(
    const float* __restrict__ x, const float* __restrict__ gup,
    const float* __restrict__ sg, const float* __restrict__ su)
{
    __shared__ __align__(16) uint32_t As[2][2][128][12];          // [buf][h/l][m][kword]
    __shared__ __align__(16) __nv_bfloat16 Bs[2][2][2][16][72];   // [buf][h/l][half][k][n]
    const int mTile = blockIdx.x, nTile = blockIdx.y, e = blockIdx.z;
    int M, offE, actBase, ldb;
    const float *pg, *pu;
    if (e < NE) {
        offE = g_off[e]; M = g_off[e + 1] - offE;
        if (mTile * 128 >= M) return;
        pg = gup + (size_t)e * H * (2 * ISZ) + nTile * 64;
        pu = pg + ISZ; ldb = 2 * ISZ; actBase = T + offE;
    } else {
        offE = 0; M = T;
        pg = sg + nTile * 64; pu = su + nTile * 64; ldb = ISZ; actBase = 0;
    }
    const int tid = threadIdx.x, lane = tid & 31, warp = tid >> 5;
    const int wm = warp & 3, wn = warp >> 2;

    // A loader
    const int arow = tid >> 1;
    const int akc = (tid & 1) * 8;
    const int aw0 = (tid & 1) * 4;
    const int lr = mTile * 128 + arow;
    const float* aptr;
    if (e < NE) aptr = x + (size_t)g_perm[offE + min(lr, M - 1)] * H + akc;
    else        aptr = x + (size_t)lr * H + akc;

    // B loader: half = tid>>7, k row = (tid>>3)&15, n0 = (tid&7)*8
    const int bhalf = tid >> 7, bkr = (tid >> 3) & 15, bn0 = (tid & 7) * 8;
    const float* bptr = (bhalf ? pu : pg) + (size_t)bkr * ldb + bn0;

    // fragment addresses
    const int tq = lane >> 3, tr = lane & 7;
    const uint32_t baseA = (uint32_t)__cvta_generic_to_shared(&As[0][0][0][0]);
    const uint32_t baseB = (uint32_t)__cvta_generic_to_shared(&Bs[0][0][0][0][0]);
    const int PA = 128 * 12 * 4, SA = 2 * PA;
    const int PB = 2 * 16 * 72 * 2, SB = 2 * PB;
    uint32_t offA[2];
#pragma unroll
    for (int mi = 0; mi < 2; mi++) {
        int row = wm * 32 + mi * 16 + (tq & 1) * 8 + tr;
        offA[mi] = (uint32_t)((row * 12 + (tq >> 1) * 4) * 4);
    }
    const int kB = (tq & 1) * 8 + tr, ngB = tq >> 1;
    uint32_t offB[2][2];
#pragma unroll
    for (int hh = 0; hh < 2; hh++)
#pragma unroll
        for (int g = 0; g < 2; g++)
            offB[hh][g] = (uint32_t)((((hh * 16) + kB) * 72 + wn * 32 + g * 16 + ngB * 8) * 2);

    float acc[2][2][4][4];
#pragma unroll
    for (int h = 0; h < 2; h++)
#pragma unroll
        for (int mi = 0; mi < 2; mi++)
#pragma unroll
            for (int ni = 0; ni < 4; ni++)
#pragma unroll
                for (int r = 0; r < 4; r++) acc[h][mi][ni][r] = 0.f;

    // prologue
    {
        float4 a0 = *(const float4*)aptr;
        float4 a1 = *(const float4*)(aptr + 4);
        float4 b0 = *(const float4*)bptr;
        float4 b1 = *(const float4*)(bptr + 4);
        uint4 hi, lo;
        pack8(a0, a1, hi, lo);
        *(uint4*)&As[0][0][arow][aw0] = hi;
        *(uint4*)&As[0][1][arow][aw0] = lo;
        pack8(b0, b1, hi, lo);
        *(uint4*)&Bs[0][0][bhalf][bkr][bn0] = hi;
        *(uint4*)&Bs[0][1][bhalf][bkr][bn0] = lo;
    }
    __syncthreads();

    const int KT = H / 16;
    for (int kt = 0; kt < KT; ++kt) {
        const int s = kt & 1;
        float4 a0, a1, b0, b1;
        if (kt + 1 < KT) {
            const float* ap = aptr + (kt + 1) * 16;
            a0 = *(const float4*)ap;
            a1 = *(const float4*)(ap + 4);
            const float* bp = bptr + (size_t)(kt + 1) * 16 * ldb;
            b0 = *(const float4*)bp;
            b1 = *(const float4*)(bp + 4);
        }

        uint32_t ah[2][4], al[2][4];
        const uint32_t aB = baseA + s * SA;
        ldsm_x4(ah[0], aB + offA[0]);
        ldsm_x4(ah[1], aB + offA[1]);
        ldsm_x4(al[0], aB + PA + offA[0]);
        ldsm_x4(al[1], aB + PA + offA[1]);
        const uint32_t bB = baseB + s * SB;
#pragma unroll
        for (int hh = 0; hh < 2; ++hh) {
#pragma unroll
            for (int g = 0; g < 2; ++g) {
                uint32_t bh4[4], bl4[4];
                ldsm_x4t(bh4, bB + offB[hh][g]);
                ldsm_x4t(bl4, bB + PB + offB[hh][g]);
#pragma unroll
                for (int sub = 0; sub < 2; ++sub) {
                    const int ni = 2 * g + sub;
                    uint32_t bh[2] = { bh4[sub * 2], bh4[sub * 2 + 1] };
                    uint32_t bl[2] = { bl4[sub * 2], bl4[sub * 2 + 1] };
#pragma unroll
                    for (int mi = 0; mi < 2; ++mi) {
                        MMA_BF16(acc[hh][mi][ni], al[mi], bh);
                        MMA_BF16(acc[hh][mi][ni], ah[mi], bl);
                        MMA_BF16(acc[hh][mi][ni], ah[mi], bh);
                    }
                }
            }
        }

        if (kt + 1 < KT) {
            const int s2 = s ^ 1;
            uint4 hi, lo;
            pack8(a0, a1, hi, lo);
            *(uint4*)&As[s2][0][arow][aw0] = hi;
            *(uint4*)&As[s2][1][arow][aw0] = lo;
            pack8(b0, b1, hi, lo);
            *(uint4*)&Bs[s2][0][bhalf][bkr][bn0] = hi;
            *(uint4*)&Bs[s2][1][bhalf][bkr][bn0] = lo;
        }
        __syncthreads();
    }

    // epilogue: act = (s*up) * silu(s*gate)
#pragma unroll
    for (int mi = 0; mi < 2; ++mi) {
        const int r0 = mTile * 128 + wm * 32 + mi * 16 + (lane >> 2);
        const int r1 = r0 + 8;
        const bool v0 = r0 < M, v1 = r1 < M;
        float s0 = 1.f, s1 = 1.f;
        if (e < NE) {
            s0 = v0 ? g_scale_perm[offE + r0] : 0.f;
            s1 = v1 ? g_scale_perm[offE + r1] : 0.f;
        }
#pragma unroll
        for (int ni = 0; ni < 4; ++ni) {
            const int col = nTile * 64 + wn * 32 + ni * 8 + (lane & 3) * 2;
            if (v0) {
                float gA = s0 * acc[0][mi][ni][0], gB = s0 * acc[0][mi][ni][1];
                float uA = s0 * acc[1][mi][ni][0], uB = s0 * acc[1][mi][ni][1];
                float a0 = uA * (gA / (1.f + expf(-gA)));
                float a1 = uB * (gB / (1.f + expf(-gB)));
                *(float2*)&g_act[(size_t)(actBase + r0) * ISZ + col] = make_float2(a0, a1);
            }
            if (v1) {
                float gA = s1 * acc[0][mi][ni][2], gB = s1 * acc[0][mi][ni][3];
                float uA = s1 * acc[1][mi][ni][2], uB = s1 * acc[1][mi][ni][3];
                float a0 = uA * (gA / (1.f + expf(-gA)));
                float a1 = uB * (gB / (1.f + expf(-gB)));
                *(float2*)&g_act[(size_t)(actBase + r1) * ISZ + col] = make_float2(a0, a1);
            }
        }
    }
}

// ---------------- GEMM2: act[M,4096] x down[4096,2048] ------------------------
__global__ __launch_bounds__(256) void gemm2_kernel(
    const float* __restrict__ dwn, const float* __restrict__ sdwn,
    float* __restrict__ out, int routed)
{
    __shared__ __align__(16) uint32_t As[2][2][128][12];
    __shared__ __align__(16) __nv_bfloat16 Bs[2][2][16][136];     // [buf][h/l][k][n]
    const int mTile = blockIdx.x, nTile = blockIdx.y;
    int M, offE, actBase;
    const float* Bd;
    if (routed) {
        const int e = blockIdx.z;
        offE = g_off[e]; M = g_off[e + 1] - offE;
        if (mTile * 128 >= M) return;
        actBase = T + offE;
        Bd = dwn + (size_t)e * ISZ * H + nTile * 128;
    } else {
        offE = 0; M = T; actBase = 0;
        Bd = sdwn + nTile * 128;
    }
    const int tid = threadIdx.x, lane = tid & 31, warp = tid >> 5;
    const int wm = warp & 3, wn = warp >> 2;

    const int arow = tid >> 1;
    const int akc = (tid & 1) * 8;
    const int aw0 = (tid & 1) * 4;
    const int lr = mTile * 128 + arow;
    const float* aptr = g_act + (size_t)(actBase + min(lr, M - 1)) * ISZ + akc;

    const int bkr = tid >> 4, bn0 = (tid & 15) * 8;
    const float* bptr = Bd + (size_t)bkr * H + bn0;

    const int tq = lane >> 3, tr = lane & 7;
    const uint32_t baseA = (uint32_t)__cvta_generic_to_shared(&As[0][0][0][0]);
    const uint32_t baseB = (uint32_t)__cvta_generic_to_shared(&Bs[0][0][0][0]);
    const int PA = 128 * 12 * 4, SA = 2 * PA;
    const int PB = 16 * 136 * 2, SB = 2 * PB;
    uint32_t offA[2];
#pragma unroll
    for (int mi = 0; mi < 2; mi++) {
        int row = wm * 32 + mi * 16 + (tq & 1) * 8 + tr;
        offA[mi] = (uint32_t)((row * 12 + (tq >> 1) * 4) * 4);
    }
    const int kB = (tq & 1) * 8 + tr, ngB = tq >> 1;
    uint32_t offB[4];
#pragma unroll
    for (int g = 0; g < 4; g++)
        offB[g] = (uint32_t)((kB * 136 + wn * 64 + g * 16 + ngB * 8) * 2);

    float acc[2][8][4];
#pragma unroll
    for (int mi = 0; mi < 2; mi++)
#pragma unroll
        for (int ni = 0; ni < 8; ni++)
#pragma unroll
            for (int r = 0; r < 4; r++) acc[mi][ni][r] = 0.f;

    {
        float4 a0 = *(const float4*)aptr;
        float4 a1 = *(const float4*)(aptr + 4);
        float4 b0 = *(const float4*)bptr;
        float4 b1 = *(const float4*)(bptr + 4);
        uint4 hi, lo;
        pack8(a0, a1, hi, lo);
        *(uint4*)&As[0][0][arow][aw0] = hi;
        *(uint4*)&As[0][1][arow][aw0] = lo;
        pack8(b0, b1, hi, lo);
        *(uint4*)&Bs[0][0][bkr][bn0] = hi;
        *(uint4*)&Bs[0][1][bkr][bn0] = lo;
    }
    __syncthreads();

    const int KT = ISZ / 16;
    for (int kt = 0; kt < KT; ++kt) {
        const int s = kt & 1;
        float4 a0, a1, b0, b1;
        if (kt + 1 < KT) {
            const float* ap = aptr + (kt + 1) * 16;
            a0 = *(const float4*)ap;
            a1 = *(const float4*)(ap + 4);
            const float* bp = bptr + (size_t)(kt + 1) * 16 * H;
            b0 = *(const float4*)bp;
            b1 = *(const float4*)(bp + 4);
        }

        uint32_t ah[2][4], al[2][4];
        const uint32_t aB = baseA + s * SA;
        ldsm_x4(ah[0], aB + offA[0]);
        ldsm_x4(ah[1], aB + offA[1]);
        ldsm_x4(al[0], aB + PA + offA[0]);
        ldsm_x4(al[1], aB + PA + offA[1]);
        const uint32_t bB = baseB + s * SB;
#pragma unroll
        for (int g = 0; g < 4; ++g) {
            uint32_t bh4[4], bl4[4];
            ldsm_x4t(bh4, bB + offB[g]);
            ldsm_x4t(bl4, bB + PB + offB[g]);
#pragma unroll
            for (int sub = 0; sub < 2; ++sub) {
                const int ni = 2 * g + sub;
                uint32_t bh[2] = { bh4[sub * 2], bh4[sub * 2 + 1] };
                uint32_t bl[2] = { bl4[sub * 2], bl4[sub * 2 + 1] };
#pragma unroll
                for (int mi = 0; mi < 2; ++mi) {
                    MMA_BF16(acc[mi][ni], al[mi], bh);
                    MMA_BF16(acc[mi][ni], ah[mi], bl);
                    MMA_BF16(acc[mi][ni], ah[mi], bh);
                }
            }
        }

        if (kt + 1 < KT) {
            const int s2 = s ^ 1;
            uint4 hi, lo;
            pack8(a0, a1, hi, lo);
            *(uint4*)&As[s2][0][arow][aw0] = hi;
            *(uint4*)&As[s2][1][arow][aw0] = lo;
            pack8(b0, b1, hi, lo);
            *(uint4*)&Bs[s2][0][bkr][bn0] = hi;
            *(uint4*)&Bs[s2][1][bkr][bn0] = lo;
        }
        __syncthreads();
    }

#pragma unroll
    for (int mi = 0; mi < 2; ++mi) {
        const int r0 = mTile * 128 + wm * 32 + mi * 16 + (lane >> 2);
        const int r1 = r0 + 8;
        const bool v0 = r0 < M, v1 = r1 < M;
        int t0 = 0, t1 = 0;
        if (routed) {
            if (v0) t0 = g_perm[offE + r0];
            if (v1) t1 = g_perm[offE + r1];
        } else { t0 = r0; t1 = r1; }
#pragma unroll
        for (int ni = 0; ni < 8; ++ni) {
            const int col = nTile * 128 + wn * 64 + ni * 8 + (lane & 3) * 2;
            if (v0) {
                float2* p = (float2*)&out[(size_t)t0 * H + col];
                if (routed) {
                    float2 v = *p;
                    v.x += acc[mi][ni][0]; v.y += acc[mi][ni][1];
                    *p = v;
                } else {
                    *p = make_float2(acc[mi][ni][0], acc[mi][ni][1]);
                }
            }
            if (v1) {
                float2* p = (float2*)&out[(size_t)t1 * H + col];
                if (routed) {
                    float2 v = *p;
                    v.x += acc[mi][ni][2]; v.y += acc[mi][ni][3];
                    *p = v;
                } else {
                    *p = make_float2(acc[mi][ni][2], acc[mi][ni][3]);
                }
            }
        }
    }
}

// ---------------- launch ------------------------------------------------------
extern "C" void kernel_launch(void* const* d_in, const int* in_sizes, int n_in,
                              void* d_out, int out_size) {
    const float* x   = (const float*)d_in[0];
    const float* rw  = (const float*)d_in[1];
    const float* gup = (const float*)d_in[2];
    const float* dwn = (const float*)d_in[3];
    const float* sg  = (const float*)d_in[4];
    const float* su  = (const float*)d_in[5];
    const float* sd  = (const float*)d_in[6];
    float* out = (float*)d_out;

    router_kernel<<<T, 256>>>(x, rw);
    bucket_kernel<<<1, 256>>>();
    gemm1_kernel<<<dim3(16, ISZ / 64, NE + 1), 256>>>(x, gup, sg, su);
    gemm2_kernel<<<dim3(16, H / 128, 1), 256>>>(dwn, sd, out, 0);   // shared: writes out
    gemm2_kernel<<<dim3(16, H / 128, NE), 256>>>(dwn, sd, out, 1);  // routed: adds
}